// round 1
// baseline (speedup 1.0000x reference)
#include <cuda_runtime.h>
#include <math.h>

// ---------------- problem dims (fixed) ----------------
// B=32, C=1536, H*W = n = 1024, hid=512, l=128, m=64, g=256
#define NB 32
#define NC 1536
#define NN 1024
#define NHID 512
#define NL 128
#define NM 64
#define NG 256

// ---------------- device scratch ----------------
__device__ float g_H[(size_t)NB * NHID * NN];    // hidden activations (reused)
__device__ float g_f[(size_t)NB * NL * NN];      // f
__device__ float g_p[(size_t)NB * NM * NN];      // p (Sinkhorn cost w/o dustbin)
__device__ float g_P[(size_t)NB * NM * NN];      // transport plan (post burst div)
__device__ float g_u[NB * (NM + 1)];
__device__ float g_v[NB * NN];
__device__ float g_norms[NB * NN];               // column L2 norms of f
__device__ float g_bw[NB * NN];                  // burst weight sums
__device__ float g_agg[NB * NL * NM];
__device__ float g_ht[NB * NHID];
__device__ float g_tk[NB * NG];

// ---------------- SGEMM: C[b] = op(A @ B[b] + bias) ----------------
// A: [M,K] row-major (weights, shared across batch)
// B: [K,N] row-major per batch (strideB), C: [M,N] per batch (strideC)
// BM=BN=128, BK=16, 256 threads, 8x8 micro-tile. N must be multiple of 128,
// K multiple of 16; M may be < 128 (guarded).
__global__ void sgemm_bias_kernel(const float* __restrict__ A,
                                  const float* __restrict__ Bg,
                                  const float* __restrict__ bias,
                                  float* __restrict__ Cg,
                                  int M, int N, int K,
                                  long strideB, long strideC, int relu)
{
    const int b = blockIdx.z;
    const float* Bm = Bg + (long)b * strideB;
    float* Cm = Cg + (long)b * strideC;
    const int n0 = blockIdx.x * 128;
    const int m0 = blockIdx.y * 128;

    __shared__ float As[16][128];
    __shared__ float Bs[16][128];

    const int tid = threadIdx.x;      // 0..255
    const int tx = tid & 15;
    const int ty = tid >> 4;

    float acc[8][8];
#pragma unroll
    for (int i = 0; i < 8; i++)
#pragma unroll
        for (int j = 0; j < 8; j++) acc[i][j] = 0.f;

    for (int k0 = 0; k0 < K; k0 += 16) {
        // A tile: 128 rows x 16 k  (512 float4)
#pragma unroll
        for (int i = 0; i < 2; i++) {
            int idx = tid + i * 256;
            int row = idx >> 2;            // 0..127
            int kk  = (idx & 3) * 4;       // 0,4,8,12
            float4 av = make_float4(0.f, 0.f, 0.f, 0.f);
            if (m0 + row < M)
                av = *reinterpret_cast<const float4*>(&A[(long)(m0 + row) * K + k0 + kk]);
            As[kk + 0][row] = av.x;
            As[kk + 1][row] = av.y;
            As[kk + 2][row] = av.z;
            As[kk + 3][row] = av.w;
        }
        // B tile: 16 k x 128 n (512 float4)
#pragma unroll
        for (int i = 0; i < 2; i++) {
            int idx = tid + i * 256;
            int kk = idx >> 5;             // 0..15
            int nn = (idx & 31) * 4;       // 0..124
            float4 bv = *reinterpret_cast<const float4*>(&Bm[(long)(k0 + kk) * N + n0 + nn]);
            *reinterpret_cast<float4*>(&Bs[kk][nn]) = bv;
        }
        __syncthreads();

#pragma unroll
        for (int k = 0; k < 16; k++) {
            float af[8], bf[8];
#pragma unroll
            for (int i = 0; i < 8; i++) af[i] = As[k][ty * 8 + i];
#pragma unroll
            for (int j = 0; j < 8; j++) bf[j] = Bs[k][tx * 8 + j];
#pragma unroll
            for (int i = 0; i < 8; i++)
#pragma unroll
                for (int j = 0; j < 8; j++)
                    acc[i][j] = fmaf(af[i], bf[j], acc[i][j]);
        }
        __syncthreads();
    }

#pragma unroll
    for (int i = 0; i < 8; i++) {
        int m = m0 + ty * 8 + i;
        if (m >= M) continue;
        float bv = bias[m];
#pragma unroll
        for (int j = 0; j < 8; j++) {
            float v = acc[i][j] + bv;
            if (relu) v = fmaxf(v, 0.f);
            Cm[(long)m * N + n0 + tx * 8 + j] = v;
        }
    }
}

// ---------------- token MLP ----------------
__global__ void tk1_kernel(const float* __restrict__ t, const float* __restrict__ W,
                           const float* __restrict__ bias)
{
    int gw = (blockIdx.x * blockDim.x + threadIdx.x) >> 5;  // warp id
    int lane = threadIdx.x & 31;
    int o = gw % NHID;
    int b = gw / NHID;
    const float* tr = t + (long)b * NC;
    const float* wr = W + (long)o * NC;
    float s = 0.f;
    for (int k = lane; k < NC; k += 32) s = fmaf(tr[k], wr[k], s);
#pragma unroll
    for (int off = 16; off > 0; off >>= 1) s += __shfl_xor_sync(0xffffffffu, s, off);
    if (lane == 0) g_ht[b * NHID + o] = fmaxf(s + bias[o], 0.f);
}

__global__ void tk2_kernel(const float* __restrict__ W, const float* __restrict__ bias)
{
    int gw = (blockIdx.x * blockDim.x + threadIdx.x) >> 5;
    int lane = threadIdx.x & 31;
    int o = gw % NG;
    int b = gw / NG;
    const float* hr = g_ht + (long)b * NHID;
    const float* wr = W + (long)o * NHID;
    float s = 0.f;
    for (int k = lane; k < NHID; k += 32) s = fmaf(hr[k], wr[k], s);
#pragma unroll
    for (int off = 16; off > 0; off >>= 1) s += __shfl_xor_sync(0xffffffffu, s, off);
    if (lane == 0) g_tk[b * NG + o] = s + bias[o];
}

// ---------------- column norms of f ----------------
__global__ void colnorm_kernel()
{
    int idx = blockIdx.x * blockDim.x + threadIdx.x;  // b*NN + j
    if (idx >= NB * NN) return;
    int b = idx >> 10;
    int j = idx & (NN - 1);
    const float* fb = g_f + (long)b * NL * NN;
    float s = 0.f;
    for (int l = 0; l < NL; l++) {
        float v = fb[(long)l * NN + j];
        s = fmaf(v, v, s);
    }
    g_norms[idx] = fmaxf(sqrtf(s), 1e-12f);
}

// ---------------- burst reweighting: bw[j] = sum_k sigmoid(a*sim[j,k]+b) ----------------
// Per block: batch z, 64x64 tile of (j,k). Gram over l=128 in 4 chunks of 32.
__global__ void burst_kernel(const float* __restrict__ pa, const float* __restrict__ pb)
{
    const int b = blockIdx.z;
    const int j0 = blockIdx.y * 64;
    const int k0 = blockIdx.x * 64;
    const float a = *pa;
    const float bb = *pb;
    const float* fb = g_f + (long)b * NL * NN;

    __shared__ float Aj[32][64];
    __shared__ float Ak[32][64];

    const int tid = threadIdx.x;
    const int tx = tid & 15;
    const int ty = tid >> 4;

    float acc[4][4];
#pragma unroll
    for (int i = 0; i < 4; i++)
#pragma unroll
        for (int j = 0; j < 4; j++) acc[i][j] = 0.f;

    for (int l0 = 0; l0 < NL; l0 += 32) {
#pragma unroll
        for (int i = 0; i < 2; i++) {
            int idx = tid + i * 256;
            int r = idx >> 4;          // 0..31
            int c = (idx & 15) * 4;    // 0..60
            *reinterpret_cast<float4*>(&Aj[r][c]) =
                *reinterpret_cast<const float4*>(&fb[(long)(l0 + r) * NN + j0 + c]);
            *reinterpret_cast<float4*>(&Ak[r][c]) =
                *reinterpret_cast<const float4*>(&fb[(long)(l0 + r) * NN + k0 + c]);
        }
        __syncthreads();
#pragma unroll
        for (int l = 0; l < 32; l++) {
            float aj[4], ak[4];
#pragma unroll
            for (int i = 0; i < 4; i++) aj[i] = Aj[l][ty * 4 + i];
#pragma unroll
            for (int j = 0; j < 4; j++) ak[j] = Ak[l][tx * 4 + j];
#pragma unroll
            for (int i = 0; i < 4; i++)
#pragma unroll
                for (int j = 0; j < 4; j++)
                    acc[i][j] = fmaf(aj[i], ak[j], acc[i][j]);
        }
        __syncthreads();
    }

    // sigmoid + row-sum, reduce across the 16 tx lanes, atomic into g_bw
    float nk[4];
#pragma unroll
    for (int j = 0; j < 4; j++) nk[j] = g_norms[b * NN + k0 + tx * 4 + j];
#pragma unroll
    for (int i = 0; i < 4; i++) {
        int j = j0 + ty * 4 + i;
        float nj = g_norms[b * NN + j];
        float s = 0.f;
#pragma unroll
        for (int jj = 0; jj < 4; jj++) {
            float sim = acc[i][jj] / (nj * nk[jj]);
            s += 1.f / (1.f + expf(-(a * sim + bb)));
        }
        // reduce over tx within the aligned 16-lane group
#pragma unroll
        for (int off = 8; off > 0; off >>= 1) s += __shfl_xor_sync(0xffffffffu, s, off);
        if (tx == 0) atomicAdd(&g_bw[b * NN + j], s);
    }
}

// ---------------- Sinkhorn (3 iterations), block per batch ----------------
__global__ void sinkhorn_kernel(const float* __restrict__ pdust)
{
    const int b = blockIdx.x;
    const float dust = *pdust;
    const float NORMC = -logf((float)(NM + NN));   // -log(1088)
    const float LOGN = logf((float)NN);

    __shared__ float su[NM + 1];
    __shared__ float sv[NN];

    const int tid = threadIdx.x;
    const int warp = tid >> 5;
    const int lane = tid & 31;
    const float* pbm = g_p + (long)b * NM * NN;

    for (int j = tid; j < NN; j += 256) sv[j] = 0.f;
    __syncthreads();

    for (int it = 0; it < 3; it++) {
        // u update: rows i = warp, warp+8, ... (65 rows over 8 warps)
        for (int i = warp; i < NM + 1; i += 8) {
            float mx = -1e30f, s = 0.f;
            for (int j = lane; j < NN; j += 32) {
                float z = (i < NM) ? pbm[(long)i * NN + j] : dust;
                float x = z + sv[j];
                if (x > mx) { s = s * expf(mx - x) + 1.f; mx = x; }
                else        { s += expf(x - mx); }
            }
#pragma unroll
            for (int off = 16; off > 0; off >>= 1) {
                float mo = __shfl_xor_sync(0xffffffffu, mx, off);
                float so = __shfl_xor_sync(0xffffffffu, s, off);
                float mm = fmaxf(mx, mo);
                s = s * expf(mx - mm) + so * expf(mo - mm);
                mx = mm;
            }
            if (lane == 0) {
                float lse = mx + logf(s);
                su[i] = ((i < NM) ? NORMC : (LOGN + NORMC)) - lse;
            }
        }
        __syncthreads();
        // v update: each thread handles 4 columns
        for (int j = tid; j < NN; j += 256) {
            float mx = -1e30f, s = 0.f;
            for (int i = 0; i < NM + 1; i++) {
                float z = (i < NM) ? pbm[(long)i * NN + j] : dust;
                float x = z + su[i];
                if (x > mx) { s = s * expf(mx - x) + 1.f; mx = x; }
                else        { s += expf(x - mx); }
            }
            sv[j] = NORMC - (mx + logf(s));
        }
        __syncthreads();
    }

    for (int j = tid; j < NN; j += 256) g_v[b * NN + j] = sv[j];
    for (int i = tid; i < NM + 1; i += 256) g_u[b * (NM + 1) + i] = su[i];
}

// ---------------- P finalize: exp(Z+u+v-norm) / bw^p ----------------
__global__ void pfinal_kernel(const float* __restrict__ pbp)
{
    const float NORMC = -logf((float)(NM + NN));
    long idx = (long)blockIdx.x * blockDim.x + threadIdx.x;  // over NB*NM*NN
    int b = (int)(idx >> 16);               // 64*1024 per batch
    int i = (int)((idx >> 10) & 63);
    int j = (int)(idx & 1023);
    float val = expf(g_p[idx] + g_u[b * (NM + 1) + i] + g_v[b * NN + j] - NORMC);
    g_P[idx] = val / powf(g_bw[b * NN + j], *pbp);
}

// ---------------- agg: agg[b,l,m] = sum_n f[b,l,n]*P[b,m,n] (warp per output) ----------------
__global__ void agg_kernel()
{
    int gw = (blockIdx.x * blockDim.x + threadIdx.x) >> 5;
    int lane = threadIdx.x & 31;
    int m = gw % NM;
    int l = (gw / NM) % NL;
    int b = gw / (NM * NL);
    const float* fr = g_f + ((long)b * NL + l) * NN;
    const float* Pr = g_P + ((long)b * NM + m) * NN;
    float s = 0.f;
    for (int n = lane; n < NN; n += 32) s = fmaf(fr[n], Pr[n], s);
#pragma unroll
    for (int off = 16; off > 0; off >>= 1) s += __shfl_xor_sync(0xffffffffu, s, off);
    if (lane == 0) g_agg[((long)b * NL + l) * NM + m] = s;
}

// ---------------- final normalize + concat, block per batch ----------------
__global__ void final_kernel(float* __restrict__ out)
{
    const int b = blockIdx.x;
    const int tid = threadIdx.x;
    __shared__ float sred[256];
    __shared__ float cnorm[NM];
    __shared__ float stk;

    // tk norm (256 elements)
    float v = g_tk[b * NG + tid];
    sred[tid] = v * v;
    __syncthreads();
    for (int s = 128; s > 0; s >>= 1) {
        if (tid < s) sred[tid] += sred[tid + s];
        __syncthreads();
    }
    if (tid == 0) stk = fmaxf(sqrtf(sred[0]), 1e-12f);
    __syncthreads();

    // agg column norms over l (64 columns of length 128)
    {
        int m = tid & 63;
        int part = tid >> 6;   // 0..3
        const float* ab = g_agg + (long)b * NL * NM;
        float s = 0.f;
        for (int l = part * 32; l < part * 32 + 32; l++) {
            float x = ab[(long)l * NM + m];
            s = fmaf(x, x, s);
        }
        sred[tid] = s;
        __syncthreads();
        if (tid < 64) {
            float tot = sred[tid] + sred[tid + 64] + sred[tid + 128] + sred[tid + 192];
            cnorm[tid] = fmaxf(sqrtf(tot), 1e-12f);
        }
        __syncthreads();
    }

    const int ROW = NG + NL * NM;   // 8448
    float* orow = out + (long)b * ROW;
    float tot = 0.f;
    for (int idx = tid; idx < ROW; idx += 256) {
        float val;
        if (idx < NG) {
            val = g_tk[b * NG + idx] / stk;
        } else {
            int r = idx - NG;
            int l = r >> 6;
            int m = r & 63;
            val = g_agg[((long)b * NL + l) * NM + m] / cnorm[m];
        }
        orow[idx] = val;
        tot += val * val;
    }
    sred[tid] = tot;
    __syncthreads();
    for (int s = 128; s > 0; s >>= 1) {
        if (tid < s) sred[tid] += sred[tid + s];
        __syncthreads();
    }
    __shared__ float stot;
    if (tid == 0) stot = fmaxf(sqrtf(sred[0]), 1e-12f);
    __syncthreads();
    for (int idx = tid; idx < ROW; idx += 256) orow[idx] /= stot;
}

// ---------------- host launcher ----------------
extern "C" void kernel_launch(void* const* d_in, const int* in_sizes, int n_in,
                              void* d_out, int out_size)
{
    (void)in_sizes; (void)n_in; (void)out_size;
    const float* x   = (const float*)d_in[0];
    const float* t   = (const float*)d_in[1];
    const float* Wc1 = (const float*)d_in[2];
    const float* bc1 = (const float*)d_in[3];
    const float* Wc2 = (const float*)d_in[4];
    const float* bc2 = (const float*)d_in[5];
    const float* Ws1 = (const float*)d_in[6];
    const float* bs1 = (const float*)d_in[7];
    const float* Ws2 = (const float*)d_in[8];
    const float* bs2 = (const float*)d_in[9];
    const float* Wt1 = (const float*)d_in[10];
    const float* bt1 = (const float*)d_in[11];
    const float* Wt2 = (const float*)d_in[12];
    const float* bt2 = (const float*)d_in[13];
    const float* dust = (const float*)d_in[14];
    const float* ba   = (const float*)d_in[15];
    const float* bbp  = (const float*)d_in[16];
    const float* bp   = (const float*)d_in[17];
    float* out = (float*)d_out;

    float *pH, *pf, *pp, *pbw;
    cudaGetSymbolAddress((void**)&pH, g_H);
    cudaGetSymbolAddress((void**)&pf, g_f);
    cudaGetSymbolAddress((void**)&pp, g_p);
    cudaGetSymbolAddress((void**)&pbw, g_bw);

    // conv stacks (batched SGEMM)
    sgemm_bias_kernel<<<dim3(NN / 128, NHID / 128, NB), 256>>>(
        Wc1, x, bc1, pH, NHID, NN, NC, (long)NC * NN, (long)NHID * NN, 1);
    sgemm_bias_kernel<<<dim3(NN / 128, 1, NB), 256>>>(
        Wc2, pH, bc2, pf, NL, NN, NHID, (long)NHID * NN, (long)NL * NN, 0);
    sgemm_bias_kernel<<<dim3(NN / 128, NHID / 128, NB), 256>>>(
        Ws1, x, bs1, pH, NHID, NN, NC, (long)NC * NN, (long)NHID * NN, 1);
    sgemm_bias_kernel<<<dim3(NN / 128, 1, NB), 256>>>(
        Ws2, pH, bs2, pp, NM, NN, NHID, (long)NHID * NN, (long)NM * NN, 0);

    // token MLP
    tk1_kernel<<<(NB * NHID * 32) / 256, 256>>>(t, Wt1, bt1);
    tk2_kernel<<<(NB * NG * 32) / 256, 256>>>(Wt2, bt2);

    // burst reweighting
    colnorm_kernel<<<(NB * NN) / 256, 256>>>();
    cudaMemsetAsync(pbw, 0, (size_t)NB * NN * sizeof(float));
    burst_kernel<<<dim3(NN / 64, NN / 64, NB), 256>>>(ba, bbp);

    // Sinkhorn + transport plan
    sinkhorn_kernel<<<NB, 256>>>(dust);
    pfinal_kernel<<<(NB * NM * NN) / 256, 256>>>(bp);

    // VLAD aggregation + final normalize/concat
    agg_kernel<<<(NB * NL * NM * 32) / 256, 256>>>();
    final_kernel<<<NB, 256>>>(out);
}

// round 2
// speedup vs baseline: 1.0000x; 1.0000x over previous
#include <cuda_runtime.h>
#include <math.h>

// ---------------- problem dims (fixed) ----------------
// B=32, C=1536, H*W = n = 1024, hid=512, l=128, m=64, g=256
#define NB 32
#define NC 1536
#define NN 1024
#define NHID 512
#define NL 128
#define NM 64
#define NG 256

// ---------------- device scratch ----------------
__device__ float g_H[(size_t)NB * NHID * NN];    // hidden activations (reused)
__device__ float g_f[(size_t)NB * NL * NN];      // f
__device__ float g_p[(size_t)NB * NM * NN];      // p (Sinkhorn cost w/o dustbin)
__device__ float g_P[(size_t)NB * NM * NN];      // transport plan (post burst div)
__device__ float g_u[NB * (NM + 1)];
__device__ float g_v[NB * NN];
__device__ float g_norms[NB * NN];               // column L2 norms of f
__device__ float g_bw[NB * NN];                  // burst weight sums
__device__ float g_agg[NB * NL * NM];
__device__ float g_ht[NB * NHID];
__device__ float g_tk[NB * NG];

// ---------------- SGEMM: C[b] = op(A @ B[b] + bias) ----------------
// A: [M,K] row-major (weights, shared across batch)
// B: [K,N] row-major per batch (strideB), C: [M,N] per batch (strideC)
// BM=BN=128, BK=16, 256 threads, 8x8 micro-tile. N must be multiple of 128,
// K multiple of 16; M may be < 128 (guarded).
__global__ void sgemm_bias_kernel(const float* __restrict__ A,
                                  const float* __restrict__ Bg,
                                  const float* __restrict__ bias,
                                  float* __restrict__ Cg,
                                  int M, int N, int K,
                                  long strideB, long strideC, int relu)
{
    const int b = blockIdx.z;
    const float* Bm = Bg + (long)b * strideB;
    float* Cm = Cg + (long)b * strideC;
    const int n0 = blockIdx.x * 128;
    const int m0 = blockIdx.y * 128;

    __shared__ float As[16][128];
    __shared__ float Bs[16][128];

    const int tid = threadIdx.x;      // 0..255
    const int tx = tid & 15;
    const int ty = tid >> 4;

    float acc[8][8];
#pragma unroll
    for (int i = 0; i < 8; i++)
#pragma unroll
        for (int j = 0; j < 8; j++) acc[i][j] = 0.f;

    for (int k0 = 0; k0 < K; k0 += 16) {
        // A tile: 128 rows x 16 k  (512 float4)
#pragma unroll
        for (int i = 0; i < 2; i++) {
            int idx = tid + i * 256;
            int row = idx >> 2;            // 0..127
            int kk  = (idx & 3) * 4;       // 0,4,8,12
            float4 av = make_float4(0.f, 0.f, 0.f, 0.f);
            if (m0 + row < M)
                av = *reinterpret_cast<const float4*>(&A[(long)(m0 + row) * K + k0 + kk]);
            As[kk + 0][row] = av.x;
            As[kk + 1][row] = av.y;
            As[kk + 2][row] = av.z;
            As[kk + 3][row] = av.w;
        }
        // B tile: 16 k x 128 n (512 float4)
#pragma unroll
        for (int i = 0; i < 2; i++) {
            int idx = tid + i * 256;
            int kk = idx >> 5;             // 0..15
            int nn = (idx & 31) * 4;       // 0..124
            float4 bv = *reinterpret_cast<const float4*>(&Bm[(long)(k0 + kk) * N + n0 + nn]);
            *reinterpret_cast<float4*>(&Bs[kk][nn]) = bv;
        }
        __syncthreads();

#pragma unroll
        for (int k = 0; k < 16; k++) {
            float af[8], bf[8];
#pragma unroll
            for (int i = 0; i < 8; i++) af[i] = As[k][ty * 8 + i];
#pragma unroll
            for (int j = 0; j < 8; j++) bf[j] = Bs[k][tx * 8 + j];
#pragma unroll
            for (int i = 0; i < 8; i++)
#pragma unroll
                for (int j = 0; j < 8; j++)
                    acc[i][j] = fmaf(af[i], bf[j], acc[i][j]);
        }
        __syncthreads();
    }

#pragma unroll
    for (int i = 0; i < 8; i++) {
        int m = m0 + ty * 8 + i;
        if (m >= M) continue;
        float bv = bias[m];
#pragma unroll
        for (int j = 0; j < 8; j++) {
            float v = acc[i][j] + bv;
            if (relu) v = fmaxf(v, 0.f);
            Cm[(long)m * N + n0 + tx * 8 + j] = v;
        }
    }
}

// ---------------- token MLP ----------------
__global__ void tk1_kernel(const float* __restrict__ t, const float* __restrict__ W,
                           const float* __restrict__ bias)
{
    int gw = (blockIdx.x * blockDim.x + threadIdx.x) >> 5;  // warp id
    int lane = threadIdx.x & 31;
    int o = gw % NHID;
    int b = gw / NHID;
    const float* tr = t + (long)b * NC;
    const float* wr = W + (long)o * NC;
    float s = 0.f;
    for (int k = lane; k < NC; k += 32) s = fmaf(tr[k], wr[k], s);
#pragma unroll
    for (int off = 16; off > 0; off >>= 1) s += __shfl_xor_sync(0xffffffffu, s, off);
    if (lane == 0) g_ht[b * NHID + o] = fmaxf(s + bias[o], 0.f);
}

__global__ void tk2_kernel(const float* __restrict__ W, const float* __restrict__ bias)
{
    int gw = (blockIdx.x * blockDim.x + threadIdx.x) >> 5;
    int lane = threadIdx.x & 31;
    int o = gw % NG;
    int b = gw / NG;
    const float* hr = g_ht + (long)b * NHID;
    const float* wr = W + (long)o * NHID;
    float s = 0.f;
    for (int k = lane; k < NHID; k += 32) s = fmaf(hr[k], wr[k], s);
#pragma unroll
    for (int off = 16; off > 0; off >>= 1) s += __shfl_xor_sync(0xffffffffu, s, off);
    if (lane == 0) g_tk[b * NG + o] = s + bias[o];
}

// ---------------- column norms of f ----------------
__global__ void colnorm_kernel()
{
    int idx = blockIdx.x * blockDim.x + threadIdx.x;  // b*NN + j
    if (idx >= NB * NN) return;
    int b = idx >> 10;
    int j = idx & (NN - 1);
    const float* fb = g_f + (long)b * NL * NN;
    float s = 0.f;
    for (int l = 0; l < NL; l++) {
        float v = fb[(long)l * NN + j];
        s = fmaf(v, v, s);
    }
    g_norms[idx] = fmaxf(sqrtf(s), 1e-12f);
}

// ---------------- burst reweighting: bw[j] = sum_k sigmoid(a*sim[j,k]+b) ----------------
// Per block: batch z, 64x64 tile of (j,k). Gram over l=128 in 4 chunks of 32.
__global__ void burst_kernel(const float* __restrict__ pa, const float* __restrict__ pb)
{
    const int b = blockIdx.z;
    const int j0 = blockIdx.y * 64;
    const int k0 = blockIdx.x * 64;
    const float a = *pa;
    const float bb = *pb;
    const float* fb = g_f + (long)b * NL * NN;

    __shared__ float Aj[32][64];
    __shared__ float Ak[32][64];

    const int tid = threadIdx.x;
    const int tx = tid & 15;
    const int ty = tid >> 4;

    float acc[4][4];
#pragma unroll
    for (int i = 0; i < 4; i++)
#pragma unroll
        for (int j = 0; j < 4; j++) acc[i][j] = 0.f;

    for (int l0 = 0; l0 < NL; l0 += 32) {
#pragma unroll
        for (int i = 0; i < 2; i++) {
            int idx = tid + i * 256;
            int r = idx >> 4;          // 0..31
            int c = (idx & 15) * 4;    // 0..60
            *reinterpret_cast<float4*>(&Aj[r][c]) =
                *reinterpret_cast<const float4*>(&fb[(long)(l0 + r) * NN + j0 + c]);
            *reinterpret_cast<float4*>(&Ak[r][c]) =
                *reinterpret_cast<const float4*>(&fb[(long)(l0 + r) * NN + k0 + c]);
        }
        __syncthreads();
#pragma unroll
        for (int l = 0; l < 32; l++) {
            float aj[4], ak[4];
#pragma unroll
            for (int i = 0; i < 4; i++) aj[i] = Aj[l][ty * 4 + i];
#pragma unroll
            for (int j = 0; j < 4; j++) ak[j] = Ak[l][tx * 4 + j];
#pragma unroll
            for (int i = 0; i < 4; i++)
#pragma unroll
                for (int j = 0; j < 4; j++)
                    acc[i][j] = fmaf(aj[i], ak[j], acc[i][j]);
        }
        __syncthreads();
    }

    // sigmoid + row-sum, reduce across the 16 tx lanes, atomic into g_bw
    float nk[4];
#pragma unroll
    for (int j = 0; j < 4; j++) nk[j] = g_norms[b * NN + k0 + tx * 4 + j];
#pragma unroll
    for (int i = 0; i < 4; i++) {
        int j = j0 + ty * 4 + i;
        float nj = g_norms[b * NN + j];
        float s = 0.f;
#pragma unroll
        for (int jj = 0; jj < 4; jj++) {
            float sim = acc[i][jj] / (nj * nk[jj]);
            s += 1.f / (1.f + expf(-(a * sim + bb)));
        }
        // reduce over tx within the aligned 16-lane group
#pragma unroll
        for (int off = 8; off > 0; off >>= 1) s += __shfl_xor_sync(0xffffffffu, s, off);
        if (tx == 0) atomicAdd(&g_bw[b * NN + j], s);
    }
}

// ---------------- Sinkhorn (3 iterations), block per batch ----------------
__global__ void sinkhorn_kernel(const float* __restrict__ pdust)
{
    const int b = blockIdx.x;
    const float dust = *pdust;
    const float NORMC = -logf((float)(NM + NN));   // -log(1088)
    const float LOGN = logf((float)NN);

    __shared__ float su[NM + 1];
    __shared__ float sv[NN];

    const int tid = threadIdx.x;
    const int warp = tid >> 5;
    const int lane = tid & 31;
    const float* pbm = g_p + (long)b * NM * NN;

    for (int j = tid; j < NN; j += 256) sv[j] = 0.f;
    __syncthreads();

    for (int it = 0; it < 3; it++) {
        // u update: rows i = warp, warp+8, ... (65 rows over 8 warps)
        for (int i = warp; i < NM + 1; i += 8) {
            float mx = -1e30f, s = 0.f;
            for (int j = lane; j < NN; j += 32) {
                float z = (i < NM) ? pbm[(long)i * NN + j] : dust;
                float x = z + sv[j];
                if (x > mx) { s = s * expf(mx - x) + 1.f; mx = x; }
                else        { s += expf(x - mx); }
            }
#pragma unroll
            for (int off = 16; off > 0; off >>= 1) {
                float mo = __shfl_xor_sync(0xffffffffu, mx, off);
                float so = __shfl_xor_sync(0xffffffffu, s, off);
                float mm = fmaxf(mx, mo);
                s = s * expf(mx - mm) + so * expf(mo - mm);
                mx = mm;
            }
            if (lane == 0) {
                float lse = mx + logf(s);
                su[i] = ((i < NM) ? NORMC : (LOGN + NORMC)) - lse;
            }
        }
        __syncthreads();
        // v update: each thread handles 4 columns
        for (int j = tid; j < NN; j += 256) {
            float mx = -1e30f, s = 0.f;
            for (int i = 0; i < NM + 1; i++) {
                float z = (i < NM) ? pbm[(long)i * NN + j] : dust;
                float x = z + su[i];
                if (x > mx) { s = s * expf(mx - x) + 1.f; mx = x; }
                else        { s += expf(x - mx); }
            }
            sv[j] = NORMC - (mx + logf(s));
        }
        __syncthreads();
    }

    for (int j = tid; j < NN; j += 256) g_v[b * NN + j] = sv[j];
    for (int i = tid; i < NM + 1; i += 256) g_u[b * (NM + 1) + i] = su[i];
}

// ---------------- P finalize: exp(Z+u+v-norm) / bw^p ----------------
__global__ void pfinal_kernel(const float* __restrict__ pbp)
{
    const float NORMC = -logf((float)(NM + NN));
    long idx = (long)blockIdx.x * blockDim.x + threadIdx.x;  // over NB*NM*NN
    int b = (int)(idx >> 16);               // 64*1024 per batch
    int i = (int)((idx >> 10) & 63);
    int j = (int)(idx & 1023);
    float val = expf(g_p[idx] + g_u[b * (NM + 1) + i] + g_v[b * NN + j] - NORMC);
    g_P[idx] = val / powf(g_bw[b * NN + j], *pbp);
}

// ---------------- agg: agg[b,l,m] = sum_n f[b,l,n]*P[b,m,n] (warp per output) ----------------
__global__ void agg_kernel()
{
    int gw = (blockIdx.x * blockDim.x + threadIdx.x) >> 5;
    int lane = threadIdx.x & 31;
    int m = gw % NM;
    int l = (gw / NM) % NL;
    int b = gw / (NM * NL);
    const float* fr = g_f + ((long)b * NL + l) * NN;
    const float* Pr = g_P + ((long)b * NM + m) * NN;
    float s = 0.f;
    for (int n = lane; n < NN; n += 32) s = fmaf(fr[n], Pr[n], s);
#pragma unroll
    for (int off = 16; off > 0; off >>= 1) s += __shfl_xor_sync(0xffffffffu, s, off);
    if (lane == 0) g_agg[((long)b * NL + l) * NM + m] = s;
}

// ---------------- final normalize + concat, block per batch ----------------
__global__ void final_kernel(float* __restrict__ out)
{
    const int b = blockIdx.x;
    const int tid = threadIdx.x;
    __shared__ float sred[256];
    __shared__ float cnorm[NM];
    __shared__ float stk;

    // tk norm (256 elements)
    float v = g_tk[b * NG + tid];
    sred[tid] = v * v;
    __syncthreads();
    for (int s = 128; s > 0; s >>= 1) {
        if (tid < s) sred[tid] += sred[tid + s];
        __syncthreads();
    }
    if (tid == 0) stk = fmaxf(sqrtf(sred[0]), 1e-12f);
    __syncthreads();

    // agg column norms over l (64 columns of length 128)
    {
        int m = tid & 63;
        int part = tid >> 6;   // 0..3
        const float* ab = g_agg + (long)b * NL * NM;
        float s = 0.f;
        for (int l = part * 32; l < part * 32 + 32; l++) {
            float x = ab[(long)l * NM + m];
            s = fmaf(x, x, s);
        }
        sred[tid] = s;
        __syncthreads();
        if (tid < 64) {
            float tot = sred[tid] + sred[tid + 64] + sred[tid + 128] + sred[tid + 192];
            cnorm[tid] = fmaxf(sqrtf(tot), 1e-12f);
        }
        __syncthreads();
    }

    const int ROW = NG + NL * NM;   // 8448
    float* orow = out + (long)b * ROW;
    float tot = 0.f;
    for (int idx = tid; idx < ROW; idx += 256) {
        float val;
        if (idx < NG) {
            val = g_tk[b * NG + idx] / stk;
        } else {
            int r = idx - NG;
            int l = r >> 6;
            int m = r & 63;
            val = g_agg[((long)b * NL + l) * NM + m] / cnorm[m];
        }
        orow[idx] = val;
        tot += val * val;
    }
    sred[tid] = tot;
    __syncthreads();
    for (int s = 128; s > 0; s >>= 1) {
        if (tid < s) sred[tid] += sred[tid + s];
        __syncthreads();
    }
    __shared__ float stot;
    if (tid == 0) stot = fmaxf(sqrtf(sred[0]), 1e-12f);
    __syncthreads();
    for (int idx = tid; idx < ROW; idx += 256) orow[idx] /= stot;
}

// ---------------- host launcher ----------------
extern "C" void kernel_launch(void* const* d_in, const int* in_sizes, int n_in,
                              void* d_out, int out_size)
{
    (void)in_sizes; (void)n_in; (void)out_size;
    const float* x   = (const float*)d_in[0];
    const float* t   = (const float*)d_in[1];
    const float* Wc1 = (const float*)d_in[2];
    const float* bc1 = (const float*)d_in[3];
    const float* Wc2 = (const float*)d_in[4];
    const float* bc2 = (const float*)d_in[5];
    const float* Ws1 = (const float*)d_in[6];
    const float* bs1 = (const float*)d_in[7];
    const float* Ws2 = (const float*)d_in[8];
    const float* bs2 = (const float*)d_in[9];
    const float* Wt1 = (const float*)d_in[10];
    const float* bt1 = (const float*)d_in[11];
    const float* Wt2 = (const float*)d_in[12];
    const float* bt2 = (const float*)d_in[13];
    const float* dust = (const float*)d_in[14];
    const float* ba   = (const float*)d_in[15];
    const float* bbp  = (const float*)d_in[16];
    const float* bp   = (const float*)d_in[17];
    float* out = (float*)d_out;

    float *pH, *pf, *pp, *pbw;
    cudaGetSymbolAddress((void**)&pH, g_H);
    cudaGetSymbolAddress((void**)&pf, g_f);
    cudaGetSymbolAddress((void**)&pp, g_p);
    cudaGetSymbolAddress((void**)&pbw, g_bw);

    // conv stacks (batched SGEMM)
    sgemm_bias_kernel<<<dim3(NN / 128, NHID / 128, NB), 256>>>(
        Wc1, x, bc1, pH, NHID, NN, NC, (long)NC * NN, (long)NHID * NN, 1);
    sgemm_bias_kernel<<<dim3(NN / 128, 1, NB), 256>>>(
        Wc2, pH, bc2, pf, NL, NN, NHID, (long)NHID * NN, (long)NL * NN, 0);
    sgemm_bias_kernel<<<dim3(NN / 128, NHID / 128, NB), 256>>>(
        Ws1, x, bs1, pH, NHID, NN, NC, (long)NC * NN, (long)NHID * NN, 1);
    sgemm_bias_kernel<<<dim3(NN / 128, 1, NB), 256>>>(
        Ws2, pH, bs2, pp, NM, NN, NHID, (long)NHID * NN, (long)NM * NN, 0);

    // token MLP
    tk1_kernel<<<(NB * NHID * 32) / 256, 256>>>(t, Wt1, bt1);
    tk2_kernel<<<(NB * NG * 32) / 256, 256>>>(Wt2, bt2);

    // burst reweighting
    colnorm_kernel<<<(NB * NN) / 256, 256>>>();
    cudaMemsetAsync(pbw, 0, (size_t)NB * NN * sizeof(float));
    burst_kernel<<<dim3(NN / 64, NN / 64, NB), 256>>>(ba, bbp);

    // Sinkhorn + transport plan
    sinkhorn_kernel<<<NB, 256>>>(dust);
    pfinal_kernel<<<(NB * NM * NN) / 256, 256>>>(bp);

    // VLAD aggregation + final normalize/concat
    agg_kernel<<<(NB * NL * NM * 32) / 256, 256>>>();
    final_kernel<<<NB, 256>>>(out);
}

// round 4
// speedup vs baseline: 2.2134x; 2.2134x over previous
#include <cuda_runtime.h>
#include <cuda_bf16.h>
#include <math.h>
#include <stdint.h>

#define NB 32
#define NC 1536
#define NN 1024
#define NHID 512
#define NL 128
#define NM 64
#define NG 256

// ---- smem tile geometry ----
#define APAD 40                       // A row stride (elems): 32 + 8 pad
#define BPAD 136                      // B row stride (elems): 128 + 8 pad
#define A_BYTES (128 * APAD * 2)      // 10240
#define B_BYTES (32 * BPAD * 2)       // 8704
#define STAGE_BYTES (2 * A_BYTES + 2 * B_BYTES)   // 37888
#define SMEM_TOTAL (2 * STAGE_BYTES)              // 75776

// ---- scratch ----
__device__ __nv_bfloat16 g_xh[(size_t)NB * NC * NN];
__device__ __nv_bfloat16 g_xl[(size_t)NB * NC * NN];
__device__ __nv_bfloat16 g_hh[(size_t)NB * NHID * NN];
__device__ __nv_bfloat16 g_hl[(size_t)NB * NHID * NN];
__device__ __nv_bfloat16 g_fh[(size_t)NB * NL * NN];
__device__ __nv_bfloat16 g_fl[(size_t)NB * NL * NN];
__device__ __nv_bfloat16 g_fnj[(size_t)NB * NN * NL];   // fn transposed [n][l] (A of burst)
__device__ __nv_bfloat16 g_fnk[(size_t)NB * NL * NN];   // fn [l][n]     (B of burst)
__device__ float         g_p  [(size_t)NB * NM * NN];
__device__ __nv_bfloat16 g_Pth[(size_t)NB * NN * NM];   // P^T [n][m] hi
__device__ __nv_bfloat16 g_Ptl[(size_t)NB * NN * NM];   // P^T lo
__device__ __nv_bfloat16 g_w1h[NHID * NC], g_w1l[NHID * NC];
__device__ __nv_bfloat16 g_w2h[NHID * NC], g_w2l[NHID * NC];
__device__ __nv_bfloat16 g_wch[NL * NHID], g_wcl[NL * NHID];
__device__ __nv_bfloat16 g_wsh[NM * NHID], g_wsl[NM * NHID];
__device__ float g_u[NB * (NM + 1)];
__device__ float g_v[NB * NN];
__device__ float g_norms[NB * NN];
__device__ float g_bw[NB * NN];
__device__ float g_agg[NB * NL * NM];
__device__ float g_tht[NB * NHID];
__device__ float g_tk[NB * NG];

__device__ __forceinline__ void split2(float v, __nv_bfloat16& h, __nv_bfloat16& l) {
    h = __float2bfloat16(v);
    l = __float2bfloat16(v - __bfloat162float(h));
}

__device__ __forceinline__ uint32_t smem_u32(const void* p) {
    uint32_t a;
    asm("{ .reg .u64 t; cvta.to.shared.u64 t, %1; cvt.u32.u64 %0, t; }" : "=r"(a) : "l"(p));
    return a;
}
__device__ __forceinline__ void cp16(uint32_t d, const void* s, bool pred) {
    int sz = pred ? 16 : 0;
    asm volatile("cp.async.cg.shared.global [%0], [%1], 16, %2;"
                 :: "r"(d), "l"(s), "r"(sz) : "memory");
}
#define CP_COMMIT() asm volatile("cp.async.commit_group;" ::: "memory")
#define CP_WAIT0()  asm volatile("cp.async.wait_group 0;" ::: "memory")

__device__ __forceinline__ void ldmx4(uint32_t* r, uint32_t a) {
    asm volatile("ldmatrix.sync.aligned.m8n8.x4.shared.b16 {%0,%1,%2,%3}, [%4];"
        : "=r"(r[0]), "=r"(r[1]), "=r"(r[2]), "=r"(r[3]) : "r"(a));
}
__device__ __forceinline__ void ldmx2t(uint32_t* r, uint32_t a) {
    asm volatile("ldmatrix.sync.aligned.m8n8.x2.trans.shared.b16 {%0,%1}, [%2];"
        : "=r"(r[0]), "=r"(r[1]) : "r"(a));
}
__device__ __forceinline__ void mma16816(float* d, const uint32_t* a, const uint32_t* b) {
    asm volatile("mma.sync.aligned.m16n8k16.row.col.f32.bf16.bf16.f32 "
        "{%0,%1,%2,%3}, {%4,%5,%6,%7}, {%8,%9}, {%0,%1,%2,%3};"
        : "+f"(d[0]), "+f"(d[1]), "+f"(d[2]), "+f"(d[3])
        : "r"(a[0]), "r"(a[1]), "r"(a[2]), "r"(a[3]), "r"(b[0]), "r"(b[1]));
}

// ================= MMA GEMM =================
// D[m][n] = sum_k A[m][k] * B[k][n] (B stored k-major rows of n).
// x3 split emulation when Al != null. BM=BN=128, BK=32, 8 warps (2x4), warp 64x32.
// mode 0: split bf16 out (+bias[m], opt relu); 1: fp32 out (+bias[m] if bias); 2: burst sigmoid-reduce.
__global__ void __launch_bounds__(256, 2) mma_gemm_kernel(
    const __nv_bfloat16* __restrict__ Ah, const __nv_bfloat16* __restrict__ Al, long sA,
    const __nv_bfloat16* __restrict__ Bh, const __nv_bfloat16* __restrict__ Bl, long sB,
    int K, int ldB, int Mvalid, int Nvalid,
    const float* __restrict__ bias, int relu, int mode,
    __nv_bfloat16* __restrict__ o0, __nv_bfloat16* __restrict__ o1,
    float* __restrict__ of, long sO, int ldo,
    const float* __restrict__ pa, const float* __restrict__ pb)
{
    extern __shared__ char smem[];
    const uint32_t su = smem_u32(smem);
    const int tid = threadIdx.x, lane = tid & 31, wid = tid >> 5;
    const int wm = wid >> 2, wn = wid & 3;
    const int bz = blockIdx.z, n0 = blockIdx.x * 128, m0 = blockIdx.y * 128;
    const bool x3 = (Al != nullptr);

    const __nv_bfloat16* A_h = Ah + (long)bz * sA + (long)m0 * K;
    const __nv_bfloat16* A_l = x3 ? Al + (long)bz * sA + (long)m0 * K : A_h;
    const __nv_bfloat16* B_h = Bh + (long)bz * sB;
    const __nv_bfloat16* B_l = x3 ? Bl + (long)bz * sB : B_h;
    const int mMax = (Mvalid - m0 < 128) ? (Mvalid - m0) : 128;

    float acc[4][4][4];
#pragma unroll
    for (int i = 0; i < 4; i++)
#pragma unroll
        for (int j = 0; j < 4; j++)
#pragma unroll
            for (int q = 0; q < 4; q++) acc[i][j][q] = 0.f;

    const int nc = K >> 5;

    // ---- prefetch macro-ish lambda ----
    auto prefetch = [&](int c, int st) {
        uint32_t sa = su + st * STAGE_BYTES;
        long kb = (long)c * 32;
#pragma unroll
        for (int i = 0; i < 2; i++) {
            int idx = tid + i * 256;
            int row = idx >> 2, cc = idx & 3;
            uint32_t doff = sa + row * (APAD * 2) + cc * 16;
            bool p = row < mMax;
            cp16(doff, A_h + (long)row * K + kb + cc * 8, p);
            if (x3) cp16(doff + A_BYTES, A_l + (long)row * K + kb + cc * 8, p);
        }
#pragma unroll
        for (int i = 0; i < 2; i++) {
            int idx = tid + i * 256;
            int row = idx >> 4, cc = idx & 15;
            uint32_t doff = sa + 2 * A_BYTES + row * (BPAD * 2) + cc * 16;
            bool p = (n0 + cc * 8) < Nvalid;
            cp16(doff, B_h + (kb + row) * (long)ldB + n0 + cc * 8, p);
            if (x3) cp16(doff + B_BYTES, B_l + (kb + row) * (long)ldB + n0 + cc * 8, p);
        }
    };

    prefetch(0, 0);
    CP_COMMIT();

    for (int c = 0; c < nc; c++) {
        CP_WAIT0();
        __syncthreads();
        if (c + 1 < nc) { prefetch(c + 1, (c + 1) & 1); CP_COMMIT(); }

        uint32_t sa = su + (c & 1) * STAGE_BYTES;
#pragma unroll
        for (int kk = 0; kk < 2; kk++) {
            uint32_t afh[4][4], afl[4][4];
#pragma unroll
            for (int mi = 0; mi < 4; mi++) {
                uint32_t ad = sa + ((wm * 64 + mi * 16 + (lane & 15)) * APAD
                                    + kk * 16 + (lane >> 4) * 8) * 2;
                ldmx4(afh[mi], ad);
                if (x3) ldmx4(afl[mi], ad + A_BYTES);
            }
#pragma unroll
            for (int ni = 0; ni < 4; ni++) {
                uint32_t bd = sa + 2 * A_BYTES
                            + (kk * 16 + (lane & 15)) * (BPAD * 2)
                            + (wn * 32 + ni * 8) * 2;
                uint32_t bfh[2], bfl[2];
                ldmx2t(bfh, bd);
                if (x3) ldmx2t(bfl, bd + B_BYTES);
#pragma unroll
                for (int mi = 0; mi < 4; mi++) {
                    mma16816(acc[mi][ni], afh[mi], bfh);
                    if (x3) {
                        mma16816(acc[mi][ni], afh[mi], bfl);
                        mma16816(acc[mi][ni], afl[mi], bfh);
                    }
                }
            }
        }
    }

    // ---- epilogue ----
    const int g = lane >> 2, tq = lane & 3;
    if (mode == 2) {
        const float a = *pa, bb = *pb;
        const bool fast = (fabsf(a) + fabsf(bb)) <= 1.0f;
#pragma unroll
        for (int mi = 0; mi < 4; mi++) {
            float r0 = 0.f, r1 = 0.f;
#pragma unroll
            for (int ni = 0; ni < 4; ni++) {
#pragma unroll
                for (int q = 0; q < 4; q++) {
                    float z = a * acc[mi][ni][q] + bb;
                    float s;
                    if (fast) {
                        float t = 0.5f * z, t2 = t * t;
                        float th = t * (1.f + t2 * (-0.3333333333f
                                   + t2 * (0.1333333333f - t2 * 0.05396825397f)));
                        s = 0.5f + 0.5f * th;
                    } else {
                        s = 1.f / (1.f + __expf(-z));
                    }
                    if (q < 2) r0 += s; else r1 += s;
                }
            }
            r0 += __shfl_xor_sync(0xffffffffu, r0, 1);
            r0 += __shfl_xor_sync(0xffffffffu, r0, 2);
            r1 += __shfl_xor_sync(0xffffffffu, r1, 1);
            r1 += __shfl_xor_sync(0xffffffffu, r1, 2);
            if (tq == 0) {
                int j = m0 + wm * 64 + mi * 16 + g;
                atomicAdd(&g_bw[bz * NN + j], r0);
                atomicAdd(&g_bw[bz * NN + j + 8], r1);
            }
        }
        return;
    }

#pragma unroll
    for (int mi = 0; mi < 4; mi++) {
        int r0 = m0 + wm * 64 + mi * 16 + g;
        int r1 = r0 + 8;
        float b0v = (bias && r0 < Mvalid) ? bias[r0] : 0.f;
        float b1v = (bias && r1 < Mvalid) ? bias[r1] : 0.f;
#pragma unroll
        for (int ni = 0; ni < 4; ni++) {
            int col = n0 + wn * 32 + ni * 8 + tq * 2;
            if (col >= Nvalid) continue;
            float v00 = acc[mi][ni][0] + b0v, v01 = acc[mi][ni][1] + b0v;
            float v10 = acc[mi][ni][2] + b1v, v11 = acc[mi][ni][3] + b1v;
            if (relu) {
                v00 = fmaxf(v00, 0.f); v01 = fmaxf(v01, 0.f);
                v10 = fmaxf(v10, 0.f); v11 = fmaxf(v11, 0.f);
            }
            if (mode == 0) {
                if (r0 < Mvalid) {
                    long off = (long)bz * sO + (long)r0 * ldo + col;
                    __nv_bfloat16 h0, l0, h1, l1;
                    split2(v00, h0, l0); split2(v01, h1, l1);
                    *reinterpret_cast<uint32_t*>(o0 + off) =
                        (uint32_t)__bfloat16_as_ushort(h0) | ((uint32_t)__bfloat16_as_ushort(h1) << 16);
                    *reinterpret_cast<uint32_t*>(o1 + off) =
                        (uint32_t)__bfloat16_as_ushort(l0) | ((uint32_t)__bfloat16_as_ushort(l1) << 16);
                }
                if (r1 < Mvalid) {
                    long off = (long)bz * sO + (long)r1 * ldo + col;
                    __nv_bfloat16 h0, l0, h1, l1;
                    split2(v10, h0, l0); split2(v11, h1, l1);
                    *reinterpret_cast<uint32_t*>(o0 + off) =
                        (uint32_t)__bfloat16_as_ushort(h0) | ((uint32_t)__bfloat16_as_ushort(h1) << 16);
                    *reinterpret_cast<uint32_t*>(o1 + off) =
                        (uint32_t)__bfloat16_as_ushort(l0) | ((uint32_t)__bfloat16_as_ushort(l1) << 16);
                }
            } else {
                if (r0 < Mvalid)
                    *reinterpret_cast<float2*>(of + (long)bz * sO + (long)r0 * ldo + col) =
                        make_float2(v00, v01);
                if (r1 < Mvalid)
                    *reinterpret_cast<float2*>(of + (long)bz * sO + (long)r1 * ldo + col) =
                        make_float2(v10, v11);
            }
        }
    }
}

// ============ conversions ============
__global__ void convw_kernel(const float* __restrict__ s, __nv_bfloat16* __restrict__ dh,
                             __nv_bfloat16* __restrict__ dl, int count)
{
    for (int i = blockIdx.x * blockDim.x + threadIdx.x; i < count; i += gridDim.x * blockDim.x) {
        __nv_bfloat16 h, l; split2(s[i], h, l);
        dh[i] = h; dl[i] = l;
    }
}

__global__ void convx_kernel(const float* __restrict__ x)
{
    long i = (long)blockIdx.x * blockDim.x + threadIdx.x;
    const long total = (long)NB * NC * NN;
    for (; i < total; i += (long)gridDim.x * blockDim.x) {
        __nv_bfloat16 h, l; split2(x[i], h, l);
        g_xh[i] = h; g_xl[i] = l;
    }
}

// ============ token MLP ============
__global__ void tk1_kernel(const float* __restrict__ t, const float* __restrict__ W,
                           const float* __restrict__ bias)
{
    int gw = (blockIdx.x * blockDim.x + threadIdx.x) >> 5;
    int lane = threadIdx.x & 31;
    int o = gw % NHID, b = gw / NHID;
    const float* tr = t + (long)b * NC;
    const float* wr = W + (long)o * NC;
    float s = 0.f;
    for (int k = lane; k < NC; k += 32) s = fmaf(tr[k], wr[k], s);
#pragma unroll
    for (int off = 16; off > 0; off >>= 1) s += __shfl_xor_sync(0xffffffffu, s, off);
    if (lane == 0) g_tht[b * NHID + o] = fmaxf(s + bias[o], 0.f);
}

__global__ void tk2_kernel(const float* __restrict__ W, const float* __restrict__ bias)
{
    int gw = (blockIdx.x * blockDim.x + threadIdx.x) >> 5;
    int lane = threadIdx.x & 31;
    int o = gw % NG, b = gw / NG;
    const float* hr = g_tht + (long)b * NHID;
    const float* wr = W + (long)o * NHID;
    float s = 0.f;
    for (int k = lane; k < NHID; k += 32) s = fmaf(hr[k], wr[k], s);
#pragma unroll
    for (int off = 16; off > 0; off >>= 1) s += __shfl_xor_sync(0xffffffffu, s, off);
    if (lane == 0) g_tk[b * NG + o] = s + bias[o];
}

// ============ column norms of f ============
__global__ void colnorm_kernel()
{
    int idx = blockIdx.x * blockDim.x + threadIdx.x;
    if (idx >= NB * NN) return;
    int b = idx >> 10, j = idx & (NN - 1);
    long base = (long)b * NL * NN + j;
    float s = 0.f;
    for (int l = 0; l < NL; l++) {
        float v = __bfloat162float(g_fh[base + (long)l * NN]) +
                  __bfloat162float(g_fl[base + (long)l * NN]);
        s = fmaf(v, v, s);
    }
    g_norms[idx] = fmaxf(sqrtf(s), 1e-12f);
}

// ============ fn: normalized f -> [l][n] (fnk) and transposed [n][l] (fnj), bf16 hi ============
__global__ void fnt_kernel()
{
    __shared__ float tile[32][33];
    int b = blockIdx.z, l0 = blockIdx.y * 32, n0 = blockIdx.x * 32;
    int tx = threadIdx.x, ty = threadIdx.y;   // (32, 8)
    long fb = (long)b * NL * NN;
#pragma unroll
    for (int i = 0; i < 4; i++) {
        int l = l0 + ty + i * 8;
        long off = fb + (long)l * NN + n0 + tx;
        tile[ty + i * 8][tx] = __bfloat162float(g_fh[off]) + __bfloat162float(g_fl[off]);
    }
    __syncthreads();
    float nv = g_norms[b * NN + n0 + tx];
#pragma unroll
    for (int i = 0; i < 4; i++) {
        int l = l0 + ty + i * 8;
        g_fnk[fb + (long)l * NN + n0 + tx] = __float2bfloat16(tile[ty + i * 8][tx] / nv);
    }
#pragma unroll
    for (int i = 0; i < 4; i++) {
        int r = ty + i * 8;          // local n
        float nv2 = g_norms[b * NN + n0 + r];
        g_fnj[((long)b * NN + n0 + r) * NL + l0 + tx] =
            __float2bfloat16(tile[tx][r] / nv2);
    }
}

// ============ Sinkhorn ============
__global__ void sinkhorn_kernel(const float* __restrict__ pdust)
{
    const int b = blockIdx.x;
    const float dust = *pdust;
    const float NORMC = -logf((float)(NM + NN));
    const float LOGN = logf((float)NN);
    __shared__ float su[NM + 1];
    __shared__ float sv[NN];
    const int tid = threadIdx.x, warp = tid >> 5, lane = tid & 31;
    const float* pbm = g_p + (long)b * NM * NN;

    for (int j = tid; j < NN; j += 256) sv[j] = 0.f;
    __syncthreads();
    for (int it = 0; it < 3; it++) {
        for (int i = warp; i < NM + 1; i += 8) {
            float mx = -1e30f, s = 0.f;
            for (int j = lane; j < NN; j += 32) {
                float z = (i < NM) ? pbm[(long)i * NN + j] : dust;
                float x = z + sv[j];
                if (x > mx) { s = s * expf(mx - x) + 1.f; mx = x; }
                else        { s += expf(x - mx); }
            }
#pragma unroll
            for (int off = 16; off > 0; off >>= 1) {
                float mo = __shfl_xor_sync(0xffffffffu, mx, off);
                float so = __shfl_xor_sync(0xffffffffu, s, off);
                float mm = fmaxf(mx, mo);
                s = s * expf(mx - mm) + so * expf(mo - mm);
                mx = mm;
            }
            if (lane == 0)
                su[i] = ((i < NM) ? NORMC : (LOGN + NORMC)) - (mx + logf(s));
        }
        __syncthreads();
        for (int j = tid; j < NN; j += 256) {
            float mx = -1e30f, s = 0.f;
            for (int i = 0; i < NM + 1; i++) {
                float z = (i < NM) ? pbm[(long)i * NN + j] : dust;
                float x = z + su[i];
                if (x > mx) { s = s * expf(mx - x) + 1.f; mx = x; }
                else        { s += expf(x - mx); }
            }
            sv[j] = NORMC - (mx + logf(s));
        }
        __syncthreads();
    }
    for (int j = tid; j < NN; j += 256) g_v[b * NN + j] = sv[j];
    for (int i = tid; i < NM + 1; i += 256) g_u[b * (NM + 1) + i] = su[i];
}

// ============ P finalize -> P^T split bf16 [b][n][m] ============
__global__ void pfinal_kernel(const float* __restrict__ pbp)
{
    const float NORMC = -logf((float)(NM + NN));
    long idx = (long)blockIdx.x * blockDim.x + threadIdx.x;
    int b = (int)(idx >> 16);
    int i = (int)((idx >> 10) & 63);
    int j = (int)(idx & 1023);
    float val = expf(g_p[idx] + g_u[b * (NM + 1) + i] + g_v[b * NN + j] - NORMC);
    val /= powf(g_bw[b * NN + j], *pbp);
    __nv_bfloat16 h, l; split2(val, h, l);
    long o = ((long)b * NN + j) * NM + i;
    g_Pth[o] = h; g_Ptl[o] = l;
}

// ============ final normalize + concat ============
__global__ void final_kernel(float* __restrict__ out)
{
    const int b = blockIdx.x, tid = threadIdx.x;
    __shared__ float sred[256];
    __shared__ float cnorm[NM];
    __shared__ float stk, stot;

    float v = g_tk[b * NG + tid];
    sred[tid] = v * v;
    __syncthreads();
    for (int s = 128; s > 0; s >>= 1) { if (tid < s) sred[tid] += sred[tid + s]; __syncthreads(); }
    if (tid == 0) stk = fmaxf(sqrtf(sred[0]), 1e-12f);
    __syncthreads();
    {
        int m = tid & 63, part = tid >> 6;
        const float* ab = g_agg + (long)b * NL * NM;
        float s = 0.f;
        for (int l = part * 32; l < part * 32 + 32; l++) {
            float x = ab[(long)l * NM + m];
            s = fmaf(x, x, s);
        }
        sred[tid] = s;
        __syncthreads();
        if (tid < 64)
            cnorm[tid] = fmaxf(sqrtf(sred[tid] + sred[tid+64] + sred[tid+128] + sred[tid+192]), 1e-12f);
        __syncthreads();
    }
    const int ROW = NG + NL * NM;
    float* orow = out + (long)b * ROW;
    float tot = 0.f;
    for (int idx = tid; idx < ROW; idx += 256) {
        float val;
        if (idx < NG) val = g_tk[b * NG + idx] / stk;
        else {
            int r = idx - NG;
            val = g_agg[((long)b * NL + (r >> 6)) * NM + (r & 63)] / cnorm[r & 63];
        }
        orow[idx] = val;
        tot += val * val;
    }
    sred[tid] = tot;
    __syncthreads();
    for (int s = 128; s > 0; s >>= 1) { if (tid < s) sred[tid] += sred[tid + s]; __syncthreads(); }
    if (tid == 0) stot = fmaxf(sqrtf(sred[0]), 1e-12f);
    __syncthreads();
    for (int idx = tid; idx < ROW; idx += 256) orow[idx] /= stot;
}

// ============ launcher ============
extern "C" void kernel_launch(void* const* d_in, const int* in_sizes, int n_in,
                              void* d_out, int out_size)
{
    (void)in_sizes; (void)n_in; (void)out_size;
    const float* x    = (const float*)d_in[0];
    const float* t    = (const float*)d_in[1];
    const float* Wc1  = (const float*)d_in[2];
    const float* bc1  = (const float*)d_in[3];
    const float* Wc2  = (const float*)d_in[4];
    const float* bc2  = (const float*)d_in[5];
    const float* Ws1  = (const float*)d_in[6];
    const float* bs1  = (const float*)d_in[7];
    const float* Ws2  = (const float*)d_in[8];
    const float* bs2  = (const float*)d_in[9];
    const float* Wt1  = (const float*)d_in[10];
    const float* bt1  = (const float*)d_in[11];
    const float* Wt2  = (const float*)d_in[12];
    const float* bt2  = (const float*)d_in[13];
    const float* dust = (const float*)d_in[14];
    const float* ba   = (const float*)d_in[15];
    const float* bbp  = (const float*)d_in[16];
    const float* bp   = (const float*)d_in[17];
    float* out = (float*)d_out;

    __nv_bfloat16 *xh, *xl, *hh, *hl, *fh, *fl, *fnj, *fnk, *Pth, *Ptl;
    __nv_bfloat16 *w1h, *w1l, *w2h, *w2l, *wch, *wcl, *wsh, *wsl;
    float *pp, *pbw, *pagg;
    cudaGetSymbolAddress((void**)&xh, g_xh);   cudaGetSymbolAddress((void**)&xl, g_xl);
    cudaGetSymbolAddress((void**)&hh, g_hh);   cudaGetSymbolAddress((void**)&hl, g_hl);
    cudaGetSymbolAddress((void**)&fh, g_fh);   cudaGetSymbolAddress((void**)&fl, g_fl);
    cudaGetSymbolAddress((void**)&fnj, g_fnj); cudaGetSymbolAddress((void**)&fnk, g_fnk);
    cudaGetSymbolAddress((void**)&Pth, g_Pth); cudaGetSymbolAddress((void**)&Ptl, g_Ptl);
    cudaGetSymbolAddress((void**)&w1h, g_w1h); cudaGetSymbolAddress((void**)&w1l, g_w1l);
    cudaGetSymbolAddress((void**)&w2h, g_w2h); cudaGetSymbolAddress((void**)&w2l, g_w2l);
    cudaGetSymbolAddress((void**)&wch, g_wch); cudaGetSymbolAddress((void**)&wcl, g_wcl);
    cudaGetSymbolAddress((void**)&wsh, g_wsh); cudaGetSymbolAddress((void**)&wsl, g_wsl);
    cudaGetSymbolAddress((void**)&pp, g_p);    cudaGetSymbolAddress((void**)&pbw, g_bw);
    cudaGetSymbolAddress((void**)&pagg, g_agg);

    cudaFuncSetAttribute(mma_gemm_kernel, cudaFuncAttributeMaxDynamicSharedMemorySize, SMEM_TOTAL);

    // splits
    convw_kernel<<<256, 256>>>(Wc1, w1h, w1l, NHID * NC);
    convw_kernel<<<256, 256>>>(Ws1, w2h, w2l, NHID * NC);
    convw_kernel<<<64, 256>>>(Wc2, wch, wcl, NL * NHID);
    convw_kernel<<<32, 256>>>(Ws2, wsh, wsl, NM * NHID);
    convx_kernel<<<8192, 256>>>(x);

    // token MLP (independent)
    tk1_kernel<<<(NB * NHID * 32) / 256, 256>>>(t, Wt1, bt1);
    tk2_kernel<<<(NB * NG * 32) / 256, 256>>>(Wt2, bt2);

    // GEMM1c: h = relu(Wc1 @ x + bc1)   [hid][n]
    mma_gemm_kernel<<<dim3(NN/128, NHID/128, NB), 256, SMEM_TOTAL>>>(
        w1h, w1l, 0, xh, xl, (long)NC * NN,
        NC, NN, NHID, NN, bc1, 1, 0, hh, hl, nullptr, (long)NHID * NN, NN, nullptr, nullptr);
    // GEMM2c: f = Wc2 @ h + bc2   [l][n]
    mma_gemm_kernel<<<dim3(NN/128, 1, NB), 256, SMEM_TOTAL>>>(
        wch, wcl, 0, hh, hl, (long)NHID * NN,
        NHID, NN, NL, NN, bc2, 0, 0, fh, fl, nullptr, (long)NL * NN, NN, nullptr, nullptr);
    // GEMM1s: h = relu(Ws1 @ x + bs1)
    mma_gemm_kernel<<<dim3(NN/128, NHID/128, NB), 256, SMEM_TOTAL>>>(
        w2h, w2l, 0, xh, xl, (long)NC * NN,
        NC, NN, NHID, NN, bs1, 1, 0, hh, hl, nullptr, (long)NHID * NN, NN, nullptr, nullptr);
    // GEMM2s: p = Ws2 @ h + bs2   [m][n] fp32
    mma_gemm_kernel<<<dim3(NN/128, 1, NB), 256, SMEM_TOTAL>>>(
        wsh, wsl, 0, hh, hl, (long)NHID * NN,
        NHID, NN, NM, NN, bs2, 0, 1, nullptr, nullptr, pp, (long)NM * NN, NN, nullptr, nullptr);

    // burst reweighting
    colnorm_kernel<<<(NB * NN) / 256, 256>>>();
    fnt_kernel<<<dim3(NN/32, NL/32, NB), dim3(32, 8)>>>();
    cudaMemsetAsync(pbw, 0, (size_t)NB * NN * sizeof(float));
    mma_gemm_kernel<<<dim3(NN/128, NN/128, NB), 256, SMEM_TOTAL>>>(
        fnj, nullptr, (long)NN * NL, fnk, nullptr, (long)NL * NN,
        NL, NN, NN, NN, nullptr, 0, 2, nullptr, nullptr, nullptr, 0, 0, ba, bbp);

    // Sinkhorn + P
    sinkhorn_kernel<<<NB, 256>>>(dust);
    pfinal_kernel<<<(NB * NM * NN) / 256, 256>>>(bp);

    // agg: agg[l][m] = sum_n f[l][n] * P^T[n][m]   fp32 out
    mma_gemm_kernel<<<dim3(1, 1, NB), 256, SMEM_TOTAL>>>(
        fh, fl, (long)NL * NN, Pth, Ptl, (long)NN * NM,
        NN, NM, NL, NM, nullptr, 0, 1, nullptr, nullptr, pagg, (long)NL * NM, NM, nullptr, nullptr);

    final_kernel<<<NB, 256>>>(out);
}